// round 13
// baseline (speedup 1.0000x reference)
#include <cuda_runtime.h>
#include <cuda_fp16.h>
#include <math.h>
#include <stdint.h>

#define HID   1024
#define BATCH 32
#define SEQ   2048
#define EDIM  2048           // 2*HID
#define ROWS  (BATCH*SEQ)    // 65536

// ---- scratch (no allocations allowed) ----
__device__ float g_hid_proj[BATCH * HID];
__device__ float g_scores[BATCH * SEQ];
__device__ uint4 g_enc_h[(size_t)ROWS * EDIM / 8];   // 268 MB, fp16-packed
__device__ uint4 g_we_h[(size_t)HID * EDIM / 8];     // 4 MB, fp16-packed

// ============================================================
// helpers
// ============================================================
__device__ __forceinline__ uint32_t smem_u32(const void* p) {
    uint32_t a;
    asm("{ .reg .u64 t; cvta.to.shared.u64 t, %1; cvt.u32.u64 %0, t; }" : "=r"(a) : "l"(p));
    return a;
}
__device__ __forceinline__ void cp16(uint32_t dst, const void* src) {
    asm volatile("cp.async.cg.shared.global [%0], [%1], 16;" :: "r"(dst), "l"(src));
}
__device__ __forceinline__ void cp_commit() {
    asm volatile("cp.async.commit_group;" ::: "memory");
}
__device__ __forceinline__ void cp_wait1() {
    asm volatile("cp.async.wait_group 1;" ::: "memory");
}
__device__ __forceinline__ void mma16816(float* c, const uint32_t* a, uint32_t b0, uint32_t b1) {
    asm volatile(
        "mma.sync.aligned.m16n8k16.row.col.f32.f16.f16.f32 "
        "{%0,%1,%2,%3}, {%4,%5,%6,%7}, {%8,%9}, {%0,%1,%2,%3};"
        : "+f"(c[0]), "+f"(c[1]), "+f"(c[2]), "+f"(c[3])
        : "r"(a[0]), "r"(a[1]), "r"(a[2]), "r"(a[3]), "r"(b0), "r"(b1));
}
#define LDSM_X4(r0, r1, r2, r3, addr) \
    asm volatile("ldmatrix.sync.aligned.m8n8.x4.shared.b16 {%0,%1,%2,%3}, [%4];" \
                 : "=r"(r0), "=r"(r1), "=r"(r2), "=r"(r3) : "r"(addr))

__device__ __forceinline__ uint32_t pack_h2(float lo, float hi) {
    __half2 h = __floats2half2_rn(lo, hi);   // x = lo (low 16 bits)
    return *(uint32_t*)&h;
}

// ============================================================
// Kernel 0a: convert encoder_outputs fp32 -> fp16 packed
// ============================================================
__global__ void cvtA_kernel(const float4* __restrict__ enc) {
    size_t idx = (size_t)blockIdx.x * 256 + threadIdx.x;   // over ROWS*EDIM/8
    float4 f0 = enc[idx * 2];
    float4 f1 = enc[idx * 2 + 1];
    uint4 o;
    o.x = pack_h2(f0.x, f0.y);
    o.y = pack_h2(f0.z, f0.w);
    o.z = pack_h2(f1.x, f1.y);
    o.w = pack_h2(f1.z, f1.w);
    g_enc_h[idx] = o;
}

// ============================================================
// Kernel 0b: convert w_e = attn_w[:, HID:3H] fp32 -> fp16 packed
// ============================================================
__global__ void cvtB_kernel(const float* __restrict__ attn_w) {
    size_t idx = (size_t)blockIdx.x * 256 + threadIdx.x;   // over HID*EDIM/8
    int h  = (int)(idx >> 8);          // EDIM/8 = 256 uint4 per row
    int j8 = (int)(idx & 255);
    const float4* src = (const float4*)(attn_w + (size_t)h * (3 * HID) + HID) + j8 * 2;
    float4 f0 = src[0];
    float4 f1 = src[1];
    uint4 o;
    o.x = pack_h2(f0.x, f0.y);
    o.y = pack_h2(f0.z, f0.w);
    o.z = pack_h2(f1.x, f1.y);
    o.w = pack_h2(f1.z, f1.w);
    g_we_h[idx] = o;
}

// ============================================================
// Kernel 1: hid_proj[b,h] = hidden[b,:] . attn_w[h, 0:H] + attn_b[h]  (fp32 exact)
// ============================================================
__global__ void hidproj_kernel(const float* __restrict__ hidden,
                               const float* __restrict__ attn_w,
                               const float* __restrict__ attn_b) {
    int b    = blockIdx.y;
    int warp = threadIdx.x >> 5;
    int lane = threadIdx.x & 31;
    int h    = blockIdx.x * 8 + warp;

    const float4* hv = (const float4*)(hidden + (size_t)b * HID);
    const float4* wv = (const float4*)(attn_w + (size_t)h * (3 * HID));

    float s = 0.f;
#pragma unroll
    for (int i = 0; i < HID / 4 / 32; i++) {
        float4 a = hv[lane + i * 32];
        float4 w = wv[lane + i * 32];
        s += a.x * w.x + a.y * w.y + a.z * w.z + a.w * w.w;
    }
#pragma unroll
    for (int o = 16; o; o >>= 1) s += __shfl_xor_sync(0xffffffffu, s, o);
    if (lane == 0) g_hid_proj[b * HID + h] = s + attn_b[h];
}

// ============================================================
// Kernel 2: zero scores
// ============================================================
__global__ void zero_scores_kernel() {
    g_scores[blockIdx.x * 1024 + threadIdx.x] = 0.f;
}

// ============================================================
// Kernel 3: scores via mma.sync fp16 m16n8k16 + ldmatrix, fused epilogue
// BM=128, BN=256, BK=64. 512 threads (16 warps, 4x4), warp tile 32x64.
// 4 warps per SMSP for latency hiding. 3-stage cp.async pipeline.
// ============================================================
#define BM  128
#define BN  256
#define BKE 64               // k elements per tile
#define NKT (EDIM / BKE)     // 32
#define LDA 36               // padded row length in words (stride 4 mod 32 banks)

#define ABUF  (BM * LDA * 4)             // 18432 B
#define BBUF  (BN * LDA * 4)             // 36864 B
#define SM_A   0
#define SM_B   (3 * ABUF)                // 55296
#define SM_HP  (SM_B + 3 * BBUF)         // 165888
#define SM_VW  (SM_HP + BN * 4)          // 166912
#define SM_SSC (SM_VW + BN * 4)          // 167936
#define SM_SZ  (SM_SSC + BM * 4)         // 168448

__device__ __forceinline__ void stage_h(uint32_t aBuf, uint32_t bBuf,
                                        int m_base, int nb, int kt, int tid) {
    const char* Ab = (const char*)g_enc_h + ((size_t)m_base * EDIM + kt * BKE) * 2;
    const char* Bb = (const char*)g_we_h + ((size_t)nb * EDIM + kt * BKE) * 2;
    const int r0 = tid >> 3;             // 0..63
    const int c  = tid & 7;
#pragma unroll
    for (int i = 0; i < 2; i++) {                        // A: 128 rows
        int row = r0 + i * 64;
        cp16(aBuf + (row * LDA + c * 4) * 4, Ab + (size_t)row * (EDIM * 2) + c * 16);
    }
#pragma unroll
    for (int i = 0; i < 4; i++) {                        // B: 256 rows
        int row = r0 + i * 64;
        cp16(bBuf + (row * LDA + c * 4) * 4, Bb + (size_t)row * (EDIM * 2) + c * 16);
    }
}

__global__ __launch_bounds__(512, 1)
void scores_h_kernel(const float* __restrict__ v_w) {
    extern __shared__ char smem[];
    const uint32_t sb = smem_u32(smem);

    const int tid    = threadIdx.x;
    const int lane   = tid & 31;
    const int wid    = tid >> 5;
    const int warp_m = wid & 3;          // 0..3 (32 rows each)
    const int warp_n = wid >> 2;         // 0..3 (64 cols each)

    const int rt     = blockIdx.y;       // 0..511
    const int b      = rt >> 4;
    const int nb     = blockIdx.x * BN;  // 0..3 n-tiles
    const int m_base = rt * BM;

    float* hp_s = (float*)(smem + SM_HP);
    float* vw_s = (float*)(smem + SM_VW);
    float* ssc  = (float*)(smem + SM_SSC);
    if (tid < BN) {
        hp_s[tid] = g_hid_proj[b * HID + nb + tid];
        vw_s[tid] = v_w[nb + tid];
    }
    if (tid < BM) ssc[tid] = 0.f;

    // ldmatrix per-lane address offsets (bytes within a buffer)
    const int l7  = lane & 7;
    const int l8  = (lane >> 3) & 1;
    const int l16 = lane >> 4;
    uint32_t offA[2], offB[4];
#pragma unroll
    for (int mt = 0; mt < 2; mt++) {
        int r = warp_m * 32 + mt * 16 + l7 + l8 * 8;
        offA[mt] = (uint32_t)(r * LDA + l16 * 4) * 4;
    }
#pragma unroll
    for (int p = 0; p < 4; p++) {
        int n = warp_n * 64 + p * 16 + l7 + l8 * 8;
        offB[p] = (uint32_t)(n * LDA + l16 * 4) * 4;
    }

    // prologue: stage kt 0,1
    stage_h(sb + SM_A, sb + SM_B, m_base, nb, 0, tid);
    cp_commit();
    stage_h(sb + SM_A + ABUF, sb + SM_B + BBUF, m_base, nb, 1, tid);
    cp_commit();

    float acc[2][8][4];
#pragma unroll
    for (int mt = 0; mt < 2; mt++)
#pragma unroll
        for (int nt = 0; nt < 8; nt++)
#pragma unroll
            for (int j = 0; j < 4; j++) acc[mt][nt][j] = 0.f;

    for (int kt = 0; kt < NKT; kt++) {
        cp_wait1();              // stage kt complete
        __syncthreads();         // also orders kt-1 reads before restaging below
        if (kt + 2 < NKT) {
            int nxt = (kt + 2) % 3;
            stage_h(sb + SM_A + nxt * ABUF, sb + SM_B + nxt * BBUF,
                    m_base, nb, kt + 2, tid);
        }
        cp_commit();

        const int cur = kt % 3;
        const uint32_t baseA = sb + SM_A + cur * ABUF;
        const uint32_t baseB = sb + SM_B + cur * BBUF;

#pragma unroll
        for (int kk = 0; kk < 4; kk++) {
            uint32_t a[2][4];
#pragma unroll
            for (int mt = 0; mt < 2; mt++)
                LDSM_X4(a[mt][0], a[mt][1], a[mt][2], a[mt][3],
                        baseA + offA[mt] + kk * 32);
#pragma unroll
            for (int p = 0; p < 4; p++) {
                uint32_t b0, b1, b2, b3;   // {b0(nt=2p), b0(nt=2p+1), b1(2p), b1(2p+1)}
                LDSM_X4(b0, b1, b2, b3, baseB + offB[p] + kk * 32);
#pragma unroll
                for (int mt = 0; mt < 2; mt++) {
                    mma16816(acc[mt][2 * p],     a[mt], b0, b2);
                    mma16816(acc[mt][2 * p + 1], a[mt], b1, b3);
                }
            }
        }
    }

    // ---- epilogue: tanh + v-dot (fp32), quad reduce, shared + global atomics ----
    __syncthreads();   // all MMA reads done; ssc zero visible
#pragma unroll
    for (int mt = 0; mt < 2; mt++) {
        float p0 = 0.f, p1 = 0.f;
#pragma unroll
        for (int nt = 0; nt < 8; nt++) {
            int c0 = warp_n * 64 + nt * 8 + 2 * (lane & 3);
            float v0 = vw_s[c0], v1 = vw_s[c0 + 1];
            float h0 = hp_s[c0], h1 = hp_s[c0 + 1];
            p0 += v0 * tanhf(h0 + acc[mt][nt][0]) + v1 * tanhf(h1 + acc[mt][nt][1]);
            p1 += v0 * tanhf(h0 + acc[mt][nt][2]) + v1 * tanhf(h1 + acc[mt][nt][3]);
        }
        p0 += __shfl_xor_sync(0xffffffffu, p0, 1);
        p0 += __shfl_xor_sync(0xffffffffu, p0, 2);
        p1 += __shfl_xor_sync(0xffffffffu, p1, 1);
        p1 += __shfl_xor_sync(0xffffffffu, p1, 2);
        if ((lane & 3) == 0) {
            int r = warp_m * 32 + mt * 16 + (lane >> 2);
            atomicAdd(&ssc[r], p0);
            atomicAdd(&ssc[r + 8], p1);
        }
    }
    __syncthreads();
    if (tid < BM) atomicAdd(&g_scores[m_base + tid], ssc[tid]);
}

// ============================================================
// Kernel 4: softmax over S per batch
// ============================================================
__global__ void softmax_kernel(float* __restrict__ out_w) {
    __shared__ float red[256];
    int b = blockIdx.x;
    int tid = threadIdx.x;

    float vals[8];
    float mx = -1e30f;
#pragma unroll
    for (int i = 0; i < 8; i++) {
        vals[i] = g_scores[b * SEQ + tid + i * 256];
        mx = fmaxf(mx, vals[i]);
    }
    red[tid] = mx;
    __syncthreads();
    for (int o = 128; o; o >>= 1) {
        if (tid < o) red[tid] = fmaxf(red[tid], red[tid + o]);
        __syncthreads();
    }
    mx = red[0];
    __syncthreads();

    float s = 0.f;
#pragma unroll
    for (int i = 0; i < 8; i++) {
        vals[i] = expf(vals[i] - mx);
        s += vals[i];
    }
    red[tid] = s;
    __syncthreads();
    for (int o = 128; o; o >>= 1) {
        if (tid < o) red[tid] += red[tid + o];
        __syncthreads();
    }
    float inv = 1.f / red[0];
#pragma unroll
    for (int i = 0; i < 8; i++)
        out_w[b * SEQ + tid + i * 256] = vals[i] * inv;
}

// ============================================================
// Kernel 5: context[b,e] = sum_s w[b,s] * enc_h[b,s,e]  (fp16 enc, fp32 accum)
// Each thread owns 2 adjacent e (one half2 column pair).
// grid (EDIM/2/256 = 4, BATCH), block 256
// ============================================================
__global__ void context_kernel(const float* __restrict__ w,
                               float* __restrict__ outc) {
    __shared__ float ws[SEQ];
    int b  = blockIdx.y;
    int e2 = blockIdx.x * 256 + threadIdx.x;     // pair index, 0..1023

    for (int i = threadIdx.x; i < SEQ; i += 256) ws[i] = w[b * SEQ + i];
    __syncthreads();

    const __half2* ep = (const __half2*)g_enc_h + (size_t)b * SEQ * (EDIM / 2) + e2;
    float ax0 = 0.f, ay0 = 0.f, ax1 = 0.f, ay1 = 0.f;
#pragma unroll 4
    for (int s = 0; s < SEQ; s += 2) {
        float2 v0 = __half22float2(ep[(size_t)(s + 0) * (EDIM / 2)]);
        float2 v1 = __half22float2(ep[(size_t)(s + 1) * (EDIM / 2)]);
        ax0 += ws[s + 0] * v0.x;  ay0 += ws[s + 0] * v0.y;
        ax1 += ws[s + 1] * v1.x;  ay1 += ws[s + 1] * v1.y;
    }
    outc[b * EDIM + e2 * 2]     = ax0 + ax1;
    outc[b * EDIM + e2 * 2 + 1] = ay0 + ay1;
}

// ============================================================
// launch
// ============================================================
extern "C" void kernel_launch(void* const* d_in, const int* in_sizes, int n_in,
                              void* d_out, int out_size) {
    const float* hidden = (const float*)d_in[0];
    const float* enc    = (const float*)d_in[1];
    const float* attn_w = (const float*)d_in[2];
    const float* attn_b = (const float*)d_in[3];
    const float* v_w    = (const float*)d_in[4];

    float* out_ctx = (float*)d_out;                  // [32, 2048]
    float* out_wts = (float*)d_out + BATCH * EDIM;   // [32, 2048]

    cudaFuncSetAttribute(scores_h_kernel,
                         cudaFuncAttributeMaxDynamicSharedMemorySize, SM_SZ);

    cvtA_kernel<<<(int)((size_t)ROWS * EDIM / 8 / 256), 256>>>((const float4*)enc);
    cvtB_kernel<<<(int)((size_t)HID * EDIM / 8 / 256), 256>>>(attn_w);
    hidproj_kernel<<<dim3(HID / 8, BATCH), 256>>>(hidden, attn_w, attn_b);
    zero_scores_kernel<<<(BATCH * SEQ) / 1024, 1024>>>();
    scores_h_kernel<<<dim3(HID / BN, ROWS / BM), 512, SM_SZ>>>(v_w);
    softmax_kernel<<<BATCH, 256>>>(out_wts);
    context_kernel<<<dim3(EDIM / 2 / 256, BATCH), 256>>>(out_wts, out_ctx);
}

// round 15
// speedup vs baseline: 1.0650x; 1.0650x over previous
#include <cuda_runtime.h>
#include <cuda_fp16.h>
#include <math.h>
#include <stdint.h>

#define HID   1024
#define BATCH 32
#define SEQ   2048
#define EDIM  2048           // 2*HID
#define ROWS  (BATCH*SEQ)    // 65536

// ---- scratch (no allocations allowed) ----
__device__ float g_hid_proj[BATCH * HID];
__device__ float g_scores[BATCH * SEQ];
__device__ uint4 g_we_h[(size_t)HID * EDIM / 8];     // 4 MB, fp16-packed w_e

// ============================================================
// helpers
// ============================================================
__device__ __forceinline__ uint32_t smem_u32(const void* p) {
    uint32_t a;
    asm("{ .reg .u64 t; cvta.to.shared.u64 t, %1; cvt.u32.u64 %0, t; }" : "=r"(a) : "l"(p));
    return a;
}
__device__ __forceinline__ void cp16(uint32_t dst, const void* src) {
    asm volatile("cp.async.cg.shared.global [%0], [%1], 16;" :: "r"(dst), "l"(src));
}
__device__ __forceinline__ void cp_commit() {
    asm volatile("cp.async.commit_group;" ::: "memory");
}
__device__ __forceinline__ void cp_wait1() {
    asm volatile("cp.async.wait_group 1;" ::: "memory");
}
__device__ __forceinline__ void mma16816(float* c, const uint32_t* a, uint32_t b0, uint32_t b1) {
    asm volatile(
        "mma.sync.aligned.m16n8k16.row.col.f32.f16.f16.f32 "
        "{%0,%1,%2,%3}, {%4,%5,%6,%7}, {%8,%9}, {%0,%1,%2,%3};"
        : "+f"(c[0]), "+f"(c[1]), "+f"(c[2]), "+f"(c[3])
        : "r"(a[0]), "r"(a[1]), "r"(a[2]), "r"(a[3]), "r"(b0), "r"(b1));
}
__device__ __forceinline__ uint32_t pack_h2(float lo, float hi) {
    __half2 h = __floats2half2_rn(lo, hi);   // x = lo (low 16 bits)
    return *(uint32_t*)&h;
}

// ============================================================
// Kernel 0b: convert w_e = attn_w[:, HID:3H] fp32 -> fp16 packed
// ============================================================
__global__ void cvtB_kernel(const float* __restrict__ attn_w) {
    size_t idx = (size_t)blockIdx.x * 256 + threadIdx.x;   // over HID*EDIM/8
    int h  = (int)(idx >> 8);          // EDIM/8 = 256 uint4 per row
    int j8 = (int)(idx & 255);
    const float4* src = (const float4*)(attn_w + (size_t)h * (3 * HID) + HID) + j8 * 2;
    float4 f0 = src[0];
    float4 f1 = src[1];
    uint4 o;
    o.x = pack_h2(f0.x, f0.y);
    o.y = pack_h2(f0.z, f0.w);
    o.z = pack_h2(f1.x, f1.y);
    o.w = pack_h2(f1.z, f1.w);
    g_we_h[idx] = o;
}

// ============================================================
// Kernel 1: hid_proj[b,h] = hidden[b,:] . attn_w[h, 0:H] + attn_b[h]  (fp32 exact)
// ============================================================
__global__ void hidproj_kernel(const float* __restrict__ hidden,
                               const float* __restrict__ attn_w,
                               const float* __restrict__ attn_b) {
    int b    = blockIdx.y;
    int warp = threadIdx.x >> 5;
    int lane = threadIdx.x & 31;
    int h    = blockIdx.x * 8 + warp;

    const float4* hv = (const float4*)(hidden + (size_t)b * HID);
    const float4* wv = (const float4*)(attn_w + (size_t)h * (3 * HID));

    float s = 0.f;
#pragma unroll
    for (int i = 0; i < HID / 4 / 32; i++) {
        float4 a = hv[lane + i * 32];
        float4 w = wv[lane + i * 32];
        s += a.x * w.x + a.y * w.y + a.z * w.z + a.w * w.w;
    }
#pragma unroll
    for (int o = 16; o; o >>= 1) s += __shfl_xor_sync(0xffffffffu, s, o);
    if (lane == 0) g_hid_proj[b * HID + h] = s + attn_b[h];
}

// ============================================================
// Kernel 2: zero scores
// ============================================================
__global__ void zero_scores_kernel() {
    g_scores[blockIdx.x * 1024 + threadIdx.x] = 0.f;
}

// ============================================================
// Kernel 3: scores via mma.sync fp16 m16n8k16, fused tanh + v-dot epilogue.
// A conversion fused: staged by LDG.128 fp32 -> pack half2 -> STS (latency
// hidden under the kk loop). B staged via cp.async from pre-converted g_we_h.
// BM=128, BN=256, BK=64. 256 threads (8 warps, 2x4), warp tile 64x64.
// 3-stage pipeline, R7 structure.
// ============================================================
#define BM  128
#define BN  256
#define BKE 64               // k elements per tile
#define NKT (EDIM / BKE)     // 32
#define LDA 36               // padded row length in words (stride 4 mod 32 banks)

#define ABUF  (BM * LDA * 4)             // 18432 B
#define BBUF  (BN * LDA * 4)             // 36864 B
#define SM_A   0
#define SM_B   (3 * ABUF)                // 55296
#define SM_HP  (SM_B + 3 * BBUF)         // 165888
#define SM_VW  (SM_HP + BN * 4)          // 166912
#define SM_SSC (SM_VW + BN * 4)          // 167936
#define SM_SZ  (SM_SSC + BM * 4)         // 168448

// B staging (cp.async, fp16 source)
__device__ __forceinline__ void stage_B(uint32_t bBuf, int nb, int kt, int tid) {
    const char* Bb = (const char*)g_we_h + ((size_t)nb * EDIM + kt * BKE) * 2;
    const int r0 = tid >> 3;
    const int c  = tid & 7;
#pragma unroll
    for (int i = 0; i < 8; i++) {                        // B: 256 rows
        int row = r0 + i * 32;
        cp16(bBuf + (row * LDA + c * 4) * 4, Bb + (size_t)row * (EDIM * 2) + c * 16);
    }
}

// A staging, synchronous (prologue only): LDG fp32 -> pack -> STS
__device__ __forceinline__ void stage_A_sync(char* smem, uint32_t aOff,
                                             const float* __restrict__ enc,
                                             int m_base, int kt, int tid) {
    const int r0 = tid >> 3;
    const int c  = tid & 7;
#pragma unroll
    for (int i = 0; i < 4; i++) {
        int row = r0 + i * 32;
        const float4* src = (const float4*)(enc + (size_t)(m_base + row) * EDIM
                                            + kt * BKE + c * 8);
        float4 f0 = src[0];
        float4 f1 = src[1];
        uint4 o;
        o.x = pack_h2(f0.x, f0.y);
        o.y = pack_h2(f0.z, f0.w);
        o.z = pack_h2(f1.x, f1.y);
        o.w = pack_h2(f1.z, f1.w);
        *(uint4*)(smem + aOff + (row * LDA + c * 4) * 4) = o;
    }
}

__global__ __launch_bounds__(256, 1)
void scores_h_kernel(const float* __restrict__ enc,
                     const float* __restrict__ v_w) {
    extern __shared__ char smem[];
    const uint32_t sb = smem_u32(smem);

    const int tid    = threadIdx.x;
    const int lane   = tid & 31;
    const int wid    = tid >> 5;
    const int warp_m = wid & 1;          // 0..1 (64 rows each)
    const int warp_n = wid >> 1;         // 0..3 (64 cols each)

    const int rt     = blockIdx.y;       // 0..511
    const int b      = rt >> 4;
    const int nb     = blockIdx.x * BN;  // 0..3 n-tiles
    const int m_base = rt * BM;

    float* hp_s = (float*)(smem + SM_HP);
    float* vw_s = (float*)(smem + SM_VW);
    float* ssc  = (float*)(smem + SM_SSC);
    hp_s[tid] = g_hid_proj[b * HID + nb + tid];
    vw_s[tid] = v_w[nb + tid];
    if (tid < BM) ssc[tid] = 0.f;

    // staging map pieces for A
    const int sr0 = tid >> 3;
    const int sc  = tid & 7;

    // prologue: stage kt 0,1 (A sync, B async)
    stage_A_sync(smem, SM_A, enc, m_base, 0, tid);
    stage_B(sb + SM_B, nb, 0, tid);
    cp_commit();
    stage_A_sync(smem, SM_A + ABUF, enc, m_base, 1, tid);
    stage_B(sb + SM_B + BBUF, nb, 1, tid);
    cp_commit();

    float acc[4][8][4];
#pragma unroll
    for (int mt = 0; mt < 4; mt++)
#pragma unroll
        for (int nt = 0; nt < 8; nt++)
#pragma unroll
            for (int j = 0; j < 4; j++) acc[mt][nt][j] = 0.f;

    for (int kt = 0; kt < NKT; kt++) {
        cp_wait1();              // B stage kt complete (A via STS + barriers)
        __syncthreads();

        const int nxt = (kt + 2) % 3;
        const bool pf = (kt + 2 < NKT);

        // issue A LDGs for kt+2 (results consumed at body end -> latency hidden)
        float4 av[8];
        if (pf) {
            const int k0 = (kt + 2) * BKE;
#pragma unroll
            for (int i = 0; i < 4; i++) {
                int row = sr0 + i * 32;
                const float4* src = (const float4*)(enc
                    + (size_t)(m_base + row) * EDIM + k0 + sc * 8);
                av[2 * i]     = src[0];
                av[2 * i + 1] = src[1];
            }
            stage_B(sb + SM_B + nxt * BBUF, nb, kt + 2, tid);
        }
        cp_commit();

        const int cur = kt % 3;
        const float* Ac = (const float*)(smem + SM_A + cur * ABUF);
        const float* Bc = (const float*)(smem + SM_B + cur * BBUF);
        const uint32_t* Aw = (const uint32_t*)Ac;
        const uint32_t* Bw = (const uint32_t*)Bc;

#pragma unroll
        for (int kk = 0; kk < 4; kk++) {
            const int wc = kk * 8 + (lane & 3);
            uint32_t a[4][4];
#pragma unroll
            for (int mt = 0; mt < 4; mt++) {
                int r = warp_m * 64 + mt * 16 + (lane >> 2);
                a[mt][0] = Aw[r * LDA + wc];
                a[mt][1] = Aw[(r + 8) * LDA + wc];
                a[mt][2] = Aw[r * LDA + wc + 4];
                a[mt][3] = Aw[(r + 8) * LDA + wc + 4];
            }
#pragma unroll
            for (int nt = 0; nt < 8; nt++) {
                int n = warp_n * 64 + nt * 8 + (lane >> 2);
                uint32_t b0 = Bw[n * LDA + wc];
                uint32_t b1 = Bw[n * LDA + wc + 4];
#pragma unroll
                for (int mt = 0; mt < 4; mt++)
                    mma16816(acc[mt][nt], a[mt], b0, b1);
            }
        }

        // pack + STS the prefetched A (into buffer nxt, last read at kt-1)
        if (pf) {
            char* dst = smem + SM_A + nxt * ABUF;
#pragma unroll
            for (int i = 0; i < 4; i++) {
                int row = sr0 + i * 32;
                uint4 o;
                o.x = pack_h2(av[2 * i].x,     av[2 * i].y);
                o.y = pack_h2(av[2 * i].z,     av[2 * i].w);
                o.z = pack_h2(av[2 * i + 1].x, av[2 * i + 1].y);
                o.w = pack_h2(av[2 * i + 1].z, av[2 * i + 1].w);
                *(uint4*)(dst + (row * LDA + sc * 4) * 4) = o;
            }
        }
        __syncthreads();         // publishes A STS; orders reads of 'cur'
    }

    // ---- epilogue: tanh + v-dot (fp32), quad reduce, shared + global atomics ----
#pragma unroll
    for (int mt = 0; mt < 4; mt++) {
        float p0 = 0.f, p1 = 0.f;
#pragma unroll
        for (int nt = 0; nt < 8; nt++) {
            int c0 = warp_n * 64 + nt * 8 + 2 * (lane & 3);
            float v0 = vw_s[c0], v1 = vw_s[c0 + 1];
            float h0 = hp_s[c0], h1 = hp_s[c0 + 1];
            p0 += v0 * tanhf(h0 + acc[mt][nt][0]) + v1 * tanhf(h1 + acc[mt][nt][1]);
            p1 += v0 * tanhf(h0 + acc[mt][nt][2]) + v1 * tanhf(h1 + acc[mt][nt][3]);
        }
        p0 += __shfl_xor_sync(0xffffffffu, p0, 1);
        p0 += __shfl_xor_sync(0xffffffffu, p0, 2);
        p1 += __shfl_xor_sync(0xffffffffu, p1, 1);
        p1 += __shfl_xor_sync(0xffffffffu, p1, 2);
        if ((lane & 3) == 0) {
            int r = warp_m * 64 + mt * 16 + (lane >> 2);
            atomicAdd(&ssc[r], p0);
            atomicAdd(&ssc[r + 8], p1);
        }
    }
    __syncthreads();
    if (tid < BM) atomicAdd(&g_scores[m_base + tid], ssc[tid]);
}

// ============================================================
// Kernel 4: softmax over S per batch
// ============================================================
__global__ void softmax_kernel(float* __restrict__ out_w) {
    __shared__ float red[256];
    int b = blockIdx.x;
    int tid = threadIdx.x;

    float vals[8];
    float mx = -1e30f;
#pragma unroll
    for (int i = 0; i < 8; i++) {
        vals[i] = g_scores[b * SEQ + tid + i * 256];
        mx = fmaxf(mx, vals[i]);
    }
    red[tid] = mx;
    __syncthreads();
    for (int o = 128; o; o >>= 1) {
        if (tid < o) red[tid] = fmaxf(red[tid], red[tid + o]);
        __syncthreads();
    }
    mx = red[0];
    __syncthreads();

    float s = 0.f;
#pragma unroll
    for (int i = 0; i < 8; i++) {
        vals[i] = expf(vals[i] - mx);
        s += vals[i];
    }
    red[tid] = s;
    __syncthreads();
    for (int o = 128; o; o >>= 1) {
        if (tid < o) red[tid] += red[tid + o];
        __syncthreads();
    }
    float inv = 1.f / red[0];
#pragma unroll
    for (int i = 0; i < 8; i++)
        out_w[b * SEQ + tid + i * 256] = vals[i] * inv;
}

// ============================================================
// Kernel 5: context[b,e] = sum_s w[b,s] * enc[b,s,e]   (fp32 exact)
// ============================================================
__global__ void context_kernel(const float* __restrict__ enc,
                               const float* __restrict__ w,
                               float* __restrict__ outc) {
    __shared__ float ws[SEQ];
    int b = blockIdx.y;
    int e = blockIdx.x * 256 + threadIdx.x;

    for (int i = threadIdx.x; i < SEQ; i += 256) ws[i] = w[b * SEQ + i];
    __syncthreads();

    const float* ep = enc + (size_t)b * SEQ * EDIM + e;
    float a0 = 0.f, a1 = 0.f, a2 = 0.f, a3 = 0.f;
    for (int s = 0; s < SEQ; s += 4) {
        a0 += ws[s + 0] * ep[(size_t)(s + 0) * EDIM];
        a1 += ws[s + 1] * ep[(size_t)(s + 1) * EDIM];
        a2 += ws[s + 2] * ep[(size_t)(s + 2) * EDIM];
        a3 += ws[s + 3] * ep[(size_t)(s + 3) * EDIM];
    }
    outc[b * EDIM + e] = (a0 + a1) + (a2 + a3);
}

// ============================================================
// launch
// ============================================================
extern "C" void kernel_launch(void* const* d_in, const int* in_sizes, int n_in,
                              void* d_out, int out_size) {
    const float* hidden = (const float*)d_in[0];
    const float* enc    = (const float*)d_in[1];
    const float* attn_w = (const float*)d_in[2];
    const float* attn_b = (const float*)d_in[3];
    const float* v_w    = (const float*)d_in[4];

    float* out_ctx = (float*)d_out;                  // [32, 2048]
    float* out_wts = (float*)d_out + BATCH * EDIM;   // [32, 2048]

    cudaFuncSetAttribute(scores_h_kernel,
                         cudaFuncAttributeMaxDynamicSharedMemorySize, SM_SZ);

    cvtB_kernel<<<(int)((size_t)HID * EDIM / 8 / 256), 256>>>(attn_w);
    hidproj_kernel<<<dim3(HID / 8, BATCH), 256>>>(hidden, attn_w, attn_b);
    zero_scores_kernel<<<(BATCH * SEQ) / 1024, 1024>>>();
    scores_h_kernel<<<dim3(HID / BN, ROWS / BM), 256, SM_SZ>>>(enc, v_w);
    softmax_kernel<<<BATCH, 256>>>(out_wts);
    context_kernel<<<dim3(EDIM / 256, BATCH), 256>>>(enc, out_wts, out_ctx);
}